// round 16
// baseline (speedup 1.0000x reference)
#include <cuda_runtime.h>
#include <cstdint>

// ---------------------------------------------------------------------------
// FeatureProjection: 4-level bilinear gather + concat
//   feat0 [16, 64,56,56], feat1 [16,128,28,28], feat2 [16,256,14,14],
//   feat3 [16,512, 7, 7], pc [16,4096,3]  ->  out [16,4096,960] fp32
//
//   R14 = R13 with the PDL trigger moved to the TOP of the transpose kernel:
//   proj CTAs co-schedule with the transpose from the start. Zero-weight
//   warps (66%) stream transpose-independent stores immediately; gather
//   warps block at cudaGridDependencySynchronize (full primary completion +
//   memory visibility is guaranteed there, independent of trigger position).
//   Kernel: warp-per-level, PPB=4 cross-iteration MLP, warp-uniform zero
//   short-circuit, __stcs streaming stores.
//   NUMERICS: XLA folds /(223/(W-1)) into * f32(1/f32(223/(W-1))).
// ---------------------------------------------------------------------------

#define B_    16
#define N_    4096
#define PPB   4

__device__ __align__(16) float g_t0[16 * 56 * 56 * 64];
__device__ __align__(16) float g_t1[16 * 28 * 28 * 128];
__device__ __align__(16) float g_t2[16 * 14 * 14 * 256];
__device__ __align__(16) float g_t3[16 * 7 * 7 * 512];

__host__ __device__ constexpr float kC0 = (float)(223.0 / 55.0);
__host__ __device__ constexpr float kC1 = (float)(223.0 / 27.0);
__host__ __device__ constexpr float kC2 = (float)(223.0 / 13.0);
__host__ __device__ constexpr float kC3 = (float)(223.0 / 6.0);

// ------------- fused transpose: [C, HW] -> [HW, C], all 4 levels ------------
__global__ void transpose_all_kernel(const float* __restrict__ f0,
                                     const float* __restrict__ f1,
                                     const float* __restrict__ f2,
                                     const float* __restrict__ f3)
{
    // fire ASAP: lets proj CTAs launch and stream their zero stores while
    // this kernel is still transposing (correctness held by the dependency
    // sync in the consumer, which waits for full grid completion).
    cudaTriggerProgrammaticLaunchCompletion();

    __shared__ float tile[32][33];

    int t = blockIdx.x;
    const float* in; float* out;
    int C, HW, stiles, local;
    if (t < 196)      { in = f0; out = g_t0; C = 64;  HW = 3136; stiles = 98; local = t; }
    else if (t < 296) { in = f1; out = g_t1; C = 128; HW = 784;  stiles = 25; local = t - 196; }
    else if (t < 352) { in = f2; out = g_t2; C = 256; HW = 196;  stiles = 7;  local = t - 296; }
    else              { in = f3; out = g_t3; C = 512; HW = 49;   stiles = 2;  local = t - 352; }

    int ctile = local / stiles;
    int stile = local - ctile * stiles;

    const int b = blockIdx.z;
    const float* bin  = in  + (size_t)b * C * HW;
    float*       bout = out + (size_t)b * C * HW;

    int s0 = stile * 32;
    int c0 = ctile * 32;

    int s = s0 + threadIdx.x;
    #pragma unroll
    for (int j = 0; j < 32; j += 8) {
        int c = c0 + threadIdx.y + j;
        if (s < HW && c < C)
            tile[threadIdx.y + j][threadIdx.x] = bin[(size_t)c * HW + s];
    }
    __syncthreads();

    int c = c0 + threadIdx.x;
    #pragma unroll
    for (int j = 0; j < 32; j += 8) {
        int ss = s0 + threadIdx.y + j;
        if (c < C && ss < HW)
            bout[(size_t)ss * C + c] = tile[threadIdx.x][threadIdx.y + j];
    }
}

// ---------------- main projection kernel: warp-per-level, PPB points -------
// warp 0 -> lvl0 (lanes 0-15), warp 1 -> lvl1, warps 2-3 -> lvl2,
// warps 4-7 -> lvl3.  out float4 layout per point: [0,16)[16,48)[48,112)[112,240)
__global__ void __launch_bounds__(256) proj_kernel(const float* __restrict__ pc,
                                                   float4* __restrict__ out)
{
    const int wid  = threadIdx.x >> 5;
    const int lane = threadIdx.x & 31;

    const float4* base;
    int H, C4, c4, out_i;
    float rscale;
    bool active = true;
    if (wid == 0)      { base = (const float4*)g_t0; H = 56; C4 = 16;
                         rscale = 1.0f / kC0; c4 = lane; out_i = c4;
                         active = (lane < 16); }
    else if (wid == 1) { base = (const float4*)g_t1; H = 28; C4 = 32;
                         rscale = 1.0f / kC1; c4 = lane; out_i = 16 + c4; }
    else if (wid < 4)  { base = (const float4*)g_t2; H = 14; C4 = 64;
                         rscale = 1.0f / kC2; c4 = (wid - 2) * 32 + lane; out_i = 48 + c4; }
    else               { base = (const float4*)g_t3; H = 7;  C4 = 128;
                         rscale = 1.0f / kC3; c4 = (wid - 4) * 32 + lane; out_i = 112 + c4; }
    const int W = H;

    #pragma unroll
    for (int it = 0; it < PPB; ++it) {
        const int point = blockIdx.x * PPB + it;
        const int b     = point >> 12;       // N = 4096

        const float* pp = pc + (size_t)point * 3;
        float X = __ldg(pp + 0);
        float Y = __ldg(pp + 1);
        float Z = __ldg(pp + 2);

        float az = fabsf(Z);
        float w = fminf(fmaxf(__fdiv_rn(420.0f * X, az) + 111.5f, 0.0f), 223.0f);
        float h = fminf(fmaxf(__fdiv_rn(420.0f * Y, az) + 111.5f, 0.0f), 223.0f);
        float x = __fmul_rn(w, rscale);
        float y = __fmul_rn(h, rscale);

        float x1f = floorf(x), x2f = ceilf(x);
        float y1f = floorf(y), y2f = ceilf(y);

        if (!active) continue;
        float4* dst = out + (size_t)point * 240 + out_i;

        // zero short-circuit: transpose-independent, overlaps the transpose
        if (x1f == x2f || y1f == y2f) {
            __stcs(dst, make_float4(0.0f, 0.0f, 0.0f, 0.0f));
            continue;
        }

        float w11 = (x2f - x) * (y2f - y);
        float w21 = (x - x1f) * (y2f - y);
        float w12 = (x2f - x) * (y - y1f);
        float w22 = (x - x1f) * (y - y1f);

        int x1 = min(max((int)x1f, 0), W - 1);
        int x2 = min(max((int)x2f, 0), W - 1);
        int y1 = min(max((int)y1f, 0), W - 1);
        int y2 = min(max((int)y2f, 0), W - 1);

        int bb = b * H * W * C4;             // batch base, float4 units
        int r1 = bb + x1 * W * C4;
        int r2 = bb + x2 * W * C4;

        // gather path must see transpose output (cheap after first wait)
        cudaGridDependencySynchronize();

        float4 v11 = __ldg(base + r1 + y1 * C4 + c4);
        float4 v21 = __ldg(base + r2 + y1 * C4 + c4);
        float4 v12 = __ldg(base + r1 + y2 * C4 + c4);
        float4 v22 = __ldg(base + r2 + y2 * C4 + c4);

        float4 r;
        r.x = v11.x * w11 + v21.x * w21 + v12.x * w12 + v22.x * w22;
        r.y = v11.y * w11 + v21.y * w21 + v12.y * w12 + v22.y * w22;
        r.z = v11.z * w11 + v21.z * w21 + v12.z * w12 + v22.z * w22;
        r.w = v11.w * w11 + v21.w * w21 + v12.w * w12 + v22.w * w22;

        __stcs(dst, r);
    }
}

// ---------------------------------------------------------------------------
extern "C" void kernel_launch(void* const* d_in, const int* in_sizes, int n_in,
                              void* d_out, int out_size)
{
    const float* f0 = (const float*)d_in[0];
    const float* f1 = (const float*)d_in[1];
    const float* f2 = (const float*)d_in[2];
    const float* f3 = (const float*)d_in[3];
    const float* pc = (const float*)d_in[4];

    dim3 tb(32, 8, 1);
    transpose_all_kernel<<<dim3(384, 1, B_), tb>>>(f0, f1, f2, f3);

    // proj with programmatic dependent launch: overlaps with the transpose.
    {
        cudaLaunchConfig_t cfg = {};
        cfg.gridDim  = dim3((B_ * N_) / PPB, 1, 1);
        cfg.blockDim = dim3(256, 1, 1);
        cfg.dynamicSmemBytes = 0;
        cudaLaunchAttribute attr[1];
        attr[0].id = cudaLaunchAttributeProgrammaticStreamSerialization;
        attr[0].val.programmaticStreamSerializationAllowed = 1;
        cfg.attrs = attr;
        cfg.numAttrs = 1;
        cudaLaunchKernelEx(&cfg, proj_kernel, pc, (float4*)d_out);
    }
}

// round 17
// speedup vs baseline: 1.0990x; 1.0990x over previous
#include <cuda_runtime.h>
#include <cstdint>

// ---------------------------------------------------------------------------
// FeatureProjection: 4-level bilinear gather + concat
//   feat0 [16, 64,56,56], feat1 [16,128,28,28], feat2 [16,256,14,14],
//   feat3 [16,512, 7, 7], pc [16,4096,3]  ->  out [16,4096,960] fp32
//
//   R17 = R14 with PPB=8: deeper per-warp chain of independent points.
//   Evidence (R12 vs R13): per-warp MLP beats occupancy for this
//   latency-bound gather kernel. chains/SM: 164 -> ~256.
//   Warp-per-level layout, warp-uniform zero short-circuit, __stcs stores,
//   PDL overlap with the NCHW->NHWC transpose.
//   NUMERICS: XLA folds /(223/(W-1)) into * f32(1/f32(223/(W-1))).
// ---------------------------------------------------------------------------

#define B_    16
#define N_    4096
#define PPB   8

__device__ __align__(16) float g_t0[16 * 56 * 56 * 64];
__device__ __align__(16) float g_t1[16 * 28 * 28 * 128];
__device__ __align__(16) float g_t2[16 * 14 * 14 * 256];
__device__ __align__(16) float g_t3[16 * 7 * 7 * 512];

__host__ __device__ constexpr float kC0 = (float)(223.0 / 55.0);
__host__ __device__ constexpr float kC1 = (float)(223.0 / 27.0);
__host__ __device__ constexpr float kC2 = (float)(223.0 / 13.0);
__host__ __device__ constexpr float kC3 = (float)(223.0 / 6.0);

// ------------- fused transpose: [C, HW] -> [HW, C], all 4 levels ------------
__global__ void transpose_all_kernel(const float* __restrict__ f0,
                                     const float* __restrict__ f1,
                                     const float* __restrict__ f2,
                                     const float* __restrict__ f3)
{
    cudaTriggerProgrammaticLaunchCompletion();

    __shared__ float tile[32][33];

    int t = blockIdx.x;
    const float* in; float* out;
    int C, HW, stiles, local;
    if (t < 196)      { in = f0; out = g_t0; C = 64;  HW = 3136; stiles = 98; local = t; }
    else if (t < 296) { in = f1; out = g_t1; C = 128; HW = 784;  stiles = 25; local = t - 196; }
    else if (t < 352) { in = f2; out = g_t2; C = 256; HW = 196;  stiles = 7;  local = t - 296; }
    else              { in = f3; out = g_t3; C = 512; HW = 49;   stiles = 2;  local = t - 352; }

    int ctile = local / stiles;
    int stile = local - ctile * stiles;

    const int b = blockIdx.z;
    const float* bin  = in  + (size_t)b * C * HW;
    float*       bout = out + (size_t)b * C * HW;

    int s0 = stile * 32;
    int c0 = ctile * 32;

    int s = s0 + threadIdx.x;
    #pragma unroll
    for (int j = 0; j < 32; j += 8) {
        int c = c0 + threadIdx.y + j;
        if (s < HW && c < C)
            tile[threadIdx.y + j][threadIdx.x] = bin[(size_t)c * HW + s];
    }
    __syncthreads();

    int c = c0 + threadIdx.x;
    #pragma unroll
    for (int j = 0; j < 32; j += 8) {
        int ss = s0 + threadIdx.y + j;
        if (c < C && ss < HW)
            bout[(size_t)ss * C + c] = tile[threadIdx.x][threadIdx.y + j];
    }
}

// ---------------- main projection kernel: warp-per-level, PPB points -------
// warp 0 -> lvl0 (lanes 0-15), warp 1 -> lvl1, warps 2-3 -> lvl2,
// warps 4-7 -> lvl3.  out float4 layout per point: [0,16)[16,48)[48,112)[112,240)
__global__ void __launch_bounds__(256) proj_kernel(const float* __restrict__ pc,
                                                   float4* __restrict__ out)
{
    const int wid  = threadIdx.x >> 5;
    const int lane = threadIdx.x & 31;

    const float4* base;
    int H, C4, c4, out_i;
    float rscale;
    bool active = true;
    if (wid == 0)      { base = (const float4*)g_t0; H = 56; C4 = 16;
                         rscale = 1.0f / kC0; c4 = lane; out_i = c4;
                         active = (lane < 16); }
    else if (wid == 1) { base = (const float4*)g_t1; H = 28; C4 = 32;
                         rscale = 1.0f / kC1; c4 = lane; out_i = 16 + c4; }
    else if (wid < 4)  { base = (const float4*)g_t2; H = 14; C4 = 64;
                         rscale = 1.0f / kC2; c4 = (wid - 2) * 32 + lane; out_i = 48 + c4; }
    else               { base = (const float4*)g_t3; H = 7;  C4 = 128;
                         rscale = 1.0f / kC3; c4 = (wid - 4) * 32 + lane; out_i = 112 + c4; }
    const int W = H;

    #pragma unroll
    for (int it = 0; it < PPB; ++it) {
        const int point = blockIdx.x * PPB + it;
        const int b     = point >> 12;       // N = 4096

        const float* pp = pc + (size_t)point * 3;
        float X = __ldg(pp + 0);
        float Y = __ldg(pp + 1);
        float Z = __ldg(pp + 2);

        float az = fabsf(Z);
        float w = fminf(fmaxf(__fdiv_rn(420.0f * X, az) + 111.5f, 0.0f), 223.0f);
        float h = fminf(fmaxf(__fdiv_rn(420.0f * Y, az) + 111.5f, 0.0f), 223.0f);
        float x = __fmul_rn(w, rscale);
        float y = __fmul_rn(h, rscale);

        float x1f = floorf(x), x2f = ceilf(x);
        float y1f = floorf(y), y2f = ceilf(y);

        if (!active) continue;
        float4* dst = out + (size_t)point * 240 + out_i;

        // zero short-circuit: transpose-independent, overlaps the transpose
        if (x1f == x2f || y1f == y2f) {
            __stcs(dst, make_float4(0.0f, 0.0f, 0.0f, 0.0f));
            continue;
        }

        float w11 = (x2f - x) * (y2f - y);
        float w21 = (x - x1f) * (y2f - y);
        float w12 = (x2f - x) * (y - y1f);
        float w22 = (x - x1f) * (y - y1f);

        int x1 = min(max((int)x1f, 0), W - 1);
        int x2 = min(max((int)x2f, 0), W - 1);
        int y1 = min(max((int)y1f, 0), W - 1);
        int y2 = min(max((int)y2f, 0), W - 1);

        int bb = b * H * W * C4;             // batch base, float4 units
        int r1 = bb + x1 * W * C4;
        int r2 = bb + x2 * W * C4;

        // gather path must see transpose output (cheap after first wait)
        cudaGridDependencySynchronize();

        float4 v11 = __ldg(base + r1 + y1 * C4 + c4);
        float4 v21 = __ldg(base + r2 + y1 * C4 + c4);
        float4 v12 = __ldg(base + r1 + y2 * C4 + c4);
        float4 v22 = __ldg(base + r2 + y2 * C4 + c4);

        float4 r;
        r.x = v11.x * w11 + v21.x * w21 + v12.x * w12 + v22.x * w22;
        r.y = v11.y * w11 + v21.y * w21 + v12.y * w12 + v22.y * w22;
        r.z = v11.z * w11 + v21.z * w21 + v12.z * w12 + v22.z * w22;
        r.w = v11.w * w11 + v21.w * w21 + v12.w * w12 + v22.w * w22;

        __stcs(dst, r);
    }
}

// ---------------------------------------------------------------------------
extern "C" void kernel_launch(void* const* d_in, const int* in_sizes, int n_in,
                              void* d_out, int out_size)
{
    const float* f0 = (const float*)d_in[0];
    const float* f1 = (const float*)d_in[1];
    const float* f2 = (const float*)d_in[2];
    const float* f3 = (const float*)d_in[3];
    const float* pc = (const float*)d_in[4];

    dim3 tb(32, 8, 1);
    transpose_all_kernel<<<dim3(384, 1, B_), tb>>>(f0, f1, f2, f3);

    // proj with programmatic dependent launch: overlaps with the transpose.
    {
        cudaLaunchConfig_t cfg = {};
        cfg.gridDim  = dim3((B_ * N_) / PPB, 1, 1);
        cfg.blockDim = dim3(256, 1, 1);
        cfg.dynamicSmemBytes = 0;
        cudaLaunchAttribute attr[1];
        attr[0].id = cudaLaunchAttributeProgrammaticStreamSerialization;
        attr[0].val.programmaticStreamSerializationAllowed = 1;
        cfg.attrs = attr;
        cfg.numAttrs = 1;
        cudaLaunchKernelEx(&cfg, proj_kernel, pc, (float4*)d_out);
    }
}